// round 3
// baseline (speedup 1.0000x reference)
#include <cuda_runtime.h>

typedef unsigned long long u64;

// ---- packed f32x2 helpers (Blackwell sm_100+: add/mul/fma .f32x2 via PTX) ----
__device__ __forceinline__ u64 pk2(float lo, float hi) {
    u64 r;
    asm("mov.b64 %0, {%1, %2};" : "=l"(r) : "f"(lo), "f"(hi));
    return r;
}
__device__ __forceinline__ void upk2(u64 a, float& lo, float& hi) {
    asm("mov.b64 {%0, %1}, %2;" : "=f"(lo), "=f"(hi) : "l"(a));
}
__device__ __forceinline__ u64 fma2(u64 a, u64 b, u64 c) {
    u64 d;
    asm("fma.rn.f32x2 %0, %1, %2, %3;" : "=l"(d) : "l"(a), "l"(b), "l"(c));
    return d;
}
__device__ __forceinline__ u64 mul2(u64 a, u64 b) {
    u64 d;
    asm("mul.rn.f32x2 %0, %1, %2;" : "=l"(d) : "l"(a), "l"(b));
    return d;
}
__device__ __forceinline__ u64 add2(u64 a, u64 b) {
    u64 d;
    asm("add.rn.f32x2 %0, %1, %2;" : "=l"(d) : "l"(a), "l"(b));
    return d;
}
// exact negation via sign-bit flip -> ALU pipe (LOP3), keeps fma pipe free
__device__ __forceinline__ u64 neg2(u64 a) { return a ^ 0x8000000080000000ULL; }

// State layout: index b in [0,64), qubit w lives at bit (5-w)  (qubit 0 = MSB,
// matching the reference's C-order (2,)*6 tensor with axis w+1 = qubit w).
// Initial state after RX encodings: amp(b) = (-i)^k * P(b), k = popcount of
// encoded bits. Real gates thereafter => track (u,v) packed in one b64 reg.
__global__ void __launch_bounds__(128) qsim6_kernel(
    const float* __restrict__ x,
    const float* __restrict__ W,
    const float* __restrict__ ab,
    float* __restrict__ out,
    int nlayers, int B)
{
    int gid = blockIdx.x * blockDim.x + threadIdx.x;
    if (gid >= B) return;

    float4 xv = reinterpret_cast<const float4*>(x)[gid];
    float c0, s0, c1, s1, c2, s2, c3, s3;
    __sincosf(0.5f * xv.x, &s0, &c0);
    __sincosf(0.5f * xv.y, &s1, &c1);
    __sincosf(0.5f * xv.z, &s2, &c2);
    __sincosf(0.5f * xv.w, &s3, &c3);
    float ca0, sa0, ca1, sa1;
    __sincosf(0.5f * ab[0], &sa0, &ca0);
    __sincosf(0.5f * ab[1], &sa1, &ca1);

    // t4[i] = product over the 4 encoded qubits (bit3 of i = qubit0, ... bit0 = qubit3)
    float f0[2] = {c0, s0}, f1[2] = {c1, s1}, f2[2] = {c2, s2}, f3[2] = {c3, s3};
    float t2[4], t3[8], t4[16];
#pragma unroll
    for (int a = 0; a < 2; a++)
#pragma unroll
        for (int b = 0; b < 2; b++) t2[a * 2 + b] = f0[a] * f1[b];
#pragma unroll
    for (int a = 0; a < 4; a++)
#pragma unroll
        for (int b = 0; b < 2; b++) t3[a * 2 + b] = t2[a] * f2[b];
#pragma unroll
    for (int a = 0; a < 8; a++)
#pragma unroll
        for (int b = 0; b < 2; b++) t4[a * 2 + b] = t3[a] * f3[b];

    // ancilla (qubit4 = bit1 of j, qubit5 = bit0 of j) after RY(ancilla_bias): |0> -> (cos, sin)
    float anc[4] = {ca0 * ca1, ca0 * sa1, sa0 * ca1, sa0 * sa1};

    u64 S[64];
#pragma unroll
    for (int b = 0; b < 64; b++) {
        const int i = b >> 2, j = b & 3;
        float P = t4[i] * anc[j];
        const int k = ((i >> 3) & 1) + ((i >> 2) & 1) + ((i >> 1) & 1) + (i & 1);
        const int km = k & 3;                        // (-i)^k phase
        if (km == 0)      S[b] = pk2(P, 0.0f);       //  +real
        else if (km == 1) S[b] = pk2(0.0f, -P);      //  -i
        else if (km == 2) S[b] = pk2(-P, 0.0f);      //  -1
        else              S[b] = pk2(0.0f, P);       //  +i
    }

    for (int l = 0; l < nlayers; l++) {
        // CNOT ring: control w -> target (w+1)%6, applied sequentially
#pragma unroll
        for (int w = 0; w < 6; w++) {
            const int cm = 1 << (5 - w);
            const int tm = 1 << (5 - ((w + 1) % 6));
#pragma unroll
            for (int b = 0; b < 64; b++) {
                if ((b & cm) && !(b & tm)) {
                    u64 t = S[b]; S[b] = S[b | tm]; S[b | tm] = t;
                }
            }
        }
        // RY(weights[l][w]) on each qubit: [c -s; s c], same real op on u and v
#pragma unroll
        for (int w = 0; w < 6; w++) {
            float s, c;
            __sincosf(0.5f * __ldg(&W[l * 6 + w]), &s, &c);
            const u64 cc = pk2(c, c);
            const u64 ss = pk2(s, s);
            const u64 ns = neg2(ss);
            const int m = 1 << (5 - w);
#pragma unroll
            for (int b = 0; b < 64; b++) {
                if (!(b & m)) {
                    u64 a0 = S[b], a1 = S[b | m];
                    S[b]     = fma2(ns, a1, mul2(cc, a0));   // c*a0 - s*a1
                    S[b | m] = fma2(ss, a0, mul2(cc, a1));   // s*a0 + c*a1
                }
            }
        }
    }

    // p_b = u_b^2 + v_b^2 (kept packed); marginalize the two ancilla qubits first
    u64 m16[16];
#pragma unroll
    for (int i = 0; i < 16; i++) {
        u64 acc = mul2(S[4 * i], S[4 * i]);
        acc = fma2(S[4 * i + 1], S[4 * i + 1], acc);
        acc = fma2(S[4 * i + 2], S[4 * i + 2], acc);
        acc = fma2(S[4 * i + 3], S[4 * i + 3], acc);
        m16[i] = acc;
    }
    // <Z_w> = sum_i sign_w(i) * m16[i]; qubit0 -> bit3 of i, ..., qubit3 -> bit0
    u64 A0 = m16[0], A1 = m16[0], A2 = m16[0], A3 = m16[0];
#pragma unroll
    for (int i = 1; i < 16; i++) {
        const u64 mi = m16[i];
        const u64 ni = neg2(mi);
        A0 = add2(A0, (i & 8) ? ni : mi);
        A1 = add2(A1, (i & 4) ? ni : mi);
        A2 = add2(A2, (i & 2) ? ni : mi);
        A3 = add2(A3, (i & 1) ? ni : mi);
    }

    float lo, hi;
    float4 o;
    upk2(A0, lo, hi); o.x = lo + hi;   // u^2 part + v^2 part
    upk2(A1, lo, hi); o.y = lo + hi;
    upk2(A2, lo, hi); o.z = lo + hi;
    upk2(A3, lo, hi); o.w = lo + hi;
    reinterpret_cast<float4*>(out)[gid] = o;
}

extern "C" void kernel_launch(void* const* d_in, const int* in_sizes, int n_in,
                              void* d_out, int out_size) {
    const float* x  = (const float*)d_in[0];   // (B, 4)
    const float* W  = (const float*)d_in[1];   // (NL, 6)
    const float* ab = (const float*)d_in[2];   // (2,)
    float* out = (float*)d_out;                // (B, 4)
    const int B = in_sizes[0] / 4;
    const int nlayers = in_sizes[1] / 6;
    const int threads = 128;
    const int blocks = (B + threads - 1) / threads;
    qsim6_kernel<<<blocks, threads>>>(x, W, ab, out, nlayers, B);
}

// round 4
// speedup vs baseline: 1.1005x; 1.1005x over previous
#include <cuda_runtime.h>

typedef unsigned long long u64;

// ---- packed f32x2 helpers (Blackwell sm_100+: add/mul/fma .f32x2 via PTX) ----
__device__ __forceinline__ u64 pk2(float lo, float hi) {
    u64 r;
    asm("mov.b64 %0, {%1, %2};" : "=l"(r) : "f"(lo), "f"(hi));
    return r;
}
__device__ __forceinline__ void upk2(u64 a, float& lo, float& hi) {
    asm("mov.b64 {%0, %1}, %2;" : "=f"(lo), "=f"(hi) : "l"(a));
}
__device__ __forceinline__ u64 fma2(u64 a, u64 b, u64 c) {
    u64 d;
    asm("fma.rn.f32x2 %0, %1, %2, %3;" : "=l"(d) : "l"(a), "l"(b), "l"(c));
    return d;
}
__device__ __forceinline__ u64 mul2(u64 a, u64 b) {
    u64 d;
    asm("mul.rn.f32x2 %0, %1, %2;" : "=l"(d) : "l"(a), "l"(b));
    return d;
}
__device__ __forceinline__ u64 add2(u64 a, u64 b) {
    u64 d;
    asm("add.rn.f32x2 %0, %1, %2;" : "=l"(d) : "l"(a), "l"(b));
    return d;
}
// exact negation via sign-bit flip -> ALU pipe (LOP3), keeps fma pipe free
__device__ __forceinline__ u64 neg2(u64 a) { return a ^ 0x8000000080000000ULL; }

// State layout: index b in [0,64), qubit w lives at bit (5-w)  (qubit 0 = MSB,
// matching the reference's C-order (2,)*6 tensor with axis w+1 = qubit w).
// Initial state after RX encodings: amp(b) = (-i)^k * P(b), k = popcount of
// encoded bits. Real gates thereafter => track (u,v) packed in one b64 reg.
__global__ void __launch_bounds__(128) qsim6_kernel(
    const float* __restrict__ x,
    const float* __restrict__ W,
    const float* __restrict__ ab,
    float* __restrict__ out,
    int nlayers, int B)
{
    int gid = blockIdx.x * blockDim.x + threadIdx.x;
    if (gid >= B) return;

    float4 xv = reinterpret_cast<const float4*>(x)[gid];
    float c0, s0, c1, s1, c2, s2, c3, s3;
    __sincosf(0.5f * xv.x, &s0, &c0);
    __sincosf(0.5f * xv.y, &s1, &c1);
    __sincosf(0.5f * xv.z, &s2, &c2);
    __sincosf(0.5f * xv.w, &s3, &c3);
    float ca0, sa0, ca1, sa1;
    __sincosf(0.5f * ab[0], &sa0, &ca0);
    __sincosf(0.5f * ab[1], &sa1, &ca1);

    // t4[i] = product over the 4 encoded qubits (bit3 of i = qubit0, ... bit0 = qubit3)
    float f0[2] = {c0, s0}, f1[2] = {c1, s1}, f2[2] = {c2, s2}, f3[2] = {c3, s3};
    float t2[4], t3[8], t4[16];
#pragma unroll
    for (int a = 0; a < 2; a++)
#pragma unroll
        for (int b = 0; b < 2; b++) t2[a * 2 + b] = f0[a] * f1[b];
#pragma unroll
    for (int a = 0; a < 4; a++)
#pragma unroll
        for (int b = 0; b < 2; b++) t3[a * 2 + b] = t2[a] * f2[b];
#pragma unroll
    for (int a = 0; a < 8; a++)
#pragma unroll
        for (int b = 0; b < 2; b++) t4[a * 2 + b] = t3[a] * f3[b];

    // ancilla (qubit4 = bit1 of j, qubit5 = bit0 of j) after RY(ancilla_bias): |0> -> (cos, sin)
    float anc[4] = {ca0 * ca1, ca0 * sa1, sa0 * ca1, sa0 * sa1};

    u64 S[64];
#pragma unroll
    for (int b = 0; b < 64; b++) {
        const int i = b >> 2, j = b & 3;
        float P = t4[i] * anc[j];
        const int k = ((i >> 3) & 1) + ((i >> 2) & 1) + ((i >> 1) & 1) + (i & 1);
        const int km = k & 3;                        // (-i)^k phase
        if (km == 0)      S[b] = pk2(P, 0.0f);       //  +real
        else if (km == 1) S[b] = pk2(0.0f, -P);      //  -i
        else if (km == 2) S[b] = pk2(-P, 0.0f);      //  -1
        else              S[b] = pk2(0.0f, P);       //  +i
    }

    for (int l = 0; l < nlayers; l++) {
        // CNOT ring: control w -> target (w+1)%6, applied sequentially
#pragma unroll
        for (int w = 0; w < 6; w++) {
            const int cm = 1 << (5 - w);
            const int tm = 1 << (5 - ((w + 1) % 6));
#pragma unroll
            for (int b = 0; b < 64; b++) {
                if ((b & cm) && !(b & tm)) {
                    u64 t = S[b]; S[b] = S[b | tm]; S[b | tm] = t;
                }
            }
        }
        // RY(weights[l][w]) on each qubit: [c -s; s c], same real op on u and v
#pragma unroll
        for (int w = 0; w < 6; w++) {
            float s, c;
            __sincosf(0.5f * __ldg(&W[l * 6 + w]), &s, &c);
            const u64 cc = pk2(c, c);
            const u64 ss = pk2(s, s);
            const u64 ns = neg2(ss);
            const int m = 1 << (5 - w);
#pragma unroll
            for (int b = 0; b < 64; b++) {
                if (!(b & m)) {
                    u64 a0 = S[b], a1 = S[b | m];
                    S[b]     = fma2(ns, a1, mul2(cc, a0));   // c*a0 - s*a1
                    S[b | m] = fma2(ss, a0, mul2(cc, a1));   // s*a0 + c*a1
                }
            }
        }
    }

    // p_b = u_b^2 + v_b^2 (kept packed); marginalize the two ancilla qubits first
    u64 m16[16];
#pragma unroll
    for (int i = 0; i < 16; i++) {
        u64 acc = mul2(S[4 * i], S[4 * i]);
        acc = fma2(S[4 * i + 1], S[4 * i + 1], acc);
        acc = fma2(S[4 * i + 2], S[4 * i + 2], acc);
        acc = fma2(S[4 * i + 3], S[4 * i + 3], acc);
        m16[i] = acc;
    }
    // <Z_w> = sum_i sign_w(i) * m16[i]; qubit0 -> bit3 of i, ..., qubit3 -> bit0
    u64 A0 = m16[0], A1 = m16[0], A2 = m16[0], A3 = m16[0];
#pragma unroll
    for (int i = 1; i < 16; i++) {
        const u64 mi = m16[i];
        const u64 ni = neg2(mi);
        A0 = add2(A0, (i & 8) ? ni : mi);
        A1 = add2(A1, (i & 4) ? ni : mi);
        A2 = add2(A2, (i & 2) ? ni : mi);
        A3 = add2(A3, (i & 1) ? ni : mi);
    }

    float lo, hi;
    float4 o;
    upk2(A0, lo, hi); o.x = lo + hi;   // u^2 part + v^2 part
    upk2(A1, lo, hi); o.y = lo + hi;
    upk2(A2, lo, hi); o.z = lo + hi;
    upk2(A3, lo, hi); o.w = lo + hi;
    reinterpret_cast<float4*>(out)[gid] = o;
}

extern "C" void kernel_launch(void* const* d_in, const int* in_sizes, int n_in,
                              void* d_out, int out_size) {
    const float* x  = (const float*)d_in[0];   // (B, 4)
    const float* W  = (const float*)d_in[1];   // (NL, 6)
    const float* ab = (const float*)d_in[2];   // (2,)
    float* out = (float*)d_out;                // (B, 4)
    const int B = in_sizes[0] / 4;
    const int nlayers = in_sizes[1] / 6;
    const int threads = 128;
    const int blocks = (B + threads - 1) / threads;
    qsim6_kernel<<<blocks, threads>>>(x, W, ab, out, nlayers, B);
}

// round 5
// speedup vs baseline: 1.1253x; 1.0226x over previous
#include <cuda_runtime.h>

typedef unsigned long long u64;

// ---- packed f32x2 helpers (Blackwell sm_100+: add/mul/fma .f32x2 via PTX) ----
__device__ __forceinline__ u64 pk2(float lo, float hi) {
    u64 r;
    asm("mov.b64 %0, {%1, %2};" : "=l"(r) : "f"(lo), "f"(hi));
    return r;
}
__device__ __forceinline__ void upk2(u64 a, float& lo, float& hi) {
    asm("mov.b64 {%0, %1}, %2;" : "=f"(lo), "=f"(hi) : "l"(a));
}
__device__ __forceinline__ u64 fma2(u64 a, u64 b, u64 c) {
    u64 d;
    asm("fma.rn.f32x2 %0, %1, %2, %3;" : "=l"(d) : "l"(a), "l"(b), "l"(c));
    return d;
}
__device__ __forceinline__ u64 mul2(u64 a, u64 b) {
    u64 d;
    asm("mul.rn.f32x2 %0, %1, %2;" : "=l"(d) : "l"(a), "l"(b));
    return d;
}
__device__ __forceinline__ u64 add2(u64 a, u64 b) {
    u64 d;
    asm("add.rn.f32x2 %0, %1, %2;" : "=l"(d) : "l"(a), "l"(b));
    return d;
}
// exact negation via sign-bit flip -> ALU pipe (LOP3), keeps fma pipe free
__device__ __forceinline__ u64 neg2(u64 a) { return a ^ 0x8000000080000000ULL; }

// State layout: index b in [0,64), qubit w lives at bit (5-w)  (qubit 0 = MSB,
// matching the reference's C-order (2,)*6 tensor with axis w+1 = qubit w).
// Initial state after RX encodings: amp(b) = (-i)^k * P(b), k = popcount of
// encoded bits. Real gates thereafter => track (u,v) packed in one b64 reg.
__global__ void __launch_bounds__(128) qsim6_kernel(
    const float* __restrict__ x,
    const float* __restrict__ W,
    const float* __restrict__ ab,
    float* __restrict__ out,
    int nlayers, int B)
{
    int gid = blockIdx.x * blockDim.x + threadIdx.x;
    if (gid >= B) return;

    float4 xv = reinterpret_cast<const float4*>(x)[gid];
    float c0, s0, c1, s1, c2, s2, c3, s3;
    __sincosf(0.5f * xv.x, &s0, &c0);
    __sincosf(0.5f * xv.y, &s1, &c1);
    __sincosf(0.5f * xv.z, &s2, &c2);
    __sincosf(0.5f * xv.w, &s3, &c3);
    float ca0, sa0, ca1, sa1;
    __sincosf(0.5f * ab[0], &sa0, &ca0);
    __sincosf(0.5f * ab[1], &sa1, &ca1);

    // t4[i] = product over the 4 encoded qubits (bit3 of i = qubit0, ... bit0 = qubit3)
    float f0[2] = {c0, s0}, f1[2] = {c1, s1}, f2[2] = {c2, s2}, f3[2] = {c3, s3};
    float t2[4], t3[8], t4[16];
#pragma unroll
    for (int a = 0; a < 2; a++)
#pragma unroll
        for (int b = 0; b < 2; b++) t2[a * 2 + b] = f0[a] * f1[b];
#pragma unroll
    for (int a = 0; a < 4; a++)
#pragma unroll
        for (int b = 0; b < 2; b++) t3[a * 2 + b] = t2[a] * f2[b];
#pragma unroll
    for (int a = 0; a < 8; a++)
#pragma unroll
        for (int b = 0; b < 2; b++) t4[a * 2 + b] = t3[a] * f3[b];

    // ancilla (qubit4 = bit1 of j, qubit5 = bit0 of j) after RY(ancilla_bias): |0> -> (cos, sin)
    float anc[4] = {ca0 * ca1, ca0 * sa1, sa0 * ca1, sa0 * sa1};

    u64 S[64];
#pragma unroll
    for (int b = 0; b < 64; b++) {
        const int i = b >> 2, j = b & 3;
        float P = t4[i] * anc[j];
        const int k = ((i >> 3) & 1) + ((i >> 2) & 1) + ((i >> 1) & 1) + (i & 1);
        const int km = k & 3;                        // (-i)^k phase
        if (km == 0)      S[b] = pk2(P, 0.0f);       //  +real
        else if (km == 1) S[b] = pk2(0.0f, -P);      //  -i
        else if (km == 2) S[b] = pk2(-P, 0.0f);      //  -1
        else              S[b] = pk2(0.0f, P);       //  +i
    }

    for (int l = 0; l < nlayers; l++) {
        // CNOT ring: control w -> target (w+1)%6, applied sequentially
#pragma unroll
        for (int w = 0; w < 6; w++) {
            const int cm = 1 << (5 - w);
            const int tm = 1 << (5 - ((w + 1) % 6));
#pragma unroll
            for (int b = 0; b < 64; b++) {
                if ((b & cm) && !(b & tm)) {
                    u64 t = S[b]; S[b] = S[b | tm]; S[b | tm] = t;
                }
            }
        }
        // RY(weights[l][w]) on each qubit: [c -s; s c], same real op on u and v
#pragma unroll
        for (int w = 0; w < 6; w++) {
            float s, c;
            __sincosf(0.5f * __ldg(&W[l * 6 + w]), &s, &c);
            const u64 cc = pk2(c, c);
            const u64 ss = pk2(s, s);
            const u64 ns = neg2(ss);
            const int m = 1 << (5 - w);
#pragma unroll
            for (int b = 0; b < 64; b++) {
                if (!(b & m)) {
                    u64 a0 = S[b], a1 = S[b | m];
                    S[b]     = fma2(ns, a1, mul2(cc, a0));   // c*a0 - s*a1
                    S[b | m] = fma2(ss, a0, mul2(cc, a1));   // s*a0 + c*a1
                }
            }
        }
    }

    // p_b = u_b^2 + v_b^2 (kept packed); marginalize the two ancilla qubits first
    u64 m16[16];
#pragma unroll
    for (int i = 0; i < 16; i++) {
        u64 acc = mul2(S[4 * i], S[4 * i]);
        acc = fma2(S[4 * i + 1], S[4 * i + 1], acc);
        acc = fma2(S[4 * i + 2], S[4 * i + 2], acc);
        acc = fma2(S[4 * i + 3], S[4 * i + 3], acc);
        m16[i] = acc;
    }
    // <Z_w> = sum_i sign_w(i) * m16[i]; qubit0 -> bit3 of i, ..., qubit3 -> bit0
    u64 A0 = m16[0], A1 = m16[0], A2 = m16[0], A3 = m16[0];
#pragma unroll
    for (int i = 1; i < 16; i++) {
        const u64 mi = m16[i];
        const u64 ni = neg2(mi);
        A0 = add2(A0, (i & 8) ? ni : mi);
        A1 = add2(A1, (i & 4) ? ni : mi);
        A2 = add2(A2, (i & 2) ? ni : mi);
        A3 = add2(A3, (i & 1) ? ni : mi);
    }

    float lo, hi;
    float4 o;
    upk2(A0, lo, hi); o.x = lo + hi;   // u^2 part + v^2 part
    upk2(A1, lo, hi); o.y = lo + hi;
    upk2(A2, lo, hi); o.z = lo + hi;
    upk2(A3, lo, hi); o.w = lo + hi;
    reinterpret_cast<float4*>(out)[gid] = o;
}

extern "C" void kernel_launch(void* const* d_in, const int* in_sizes, int n_in,
                              void* d_out, int out_size) {
    const float* x  = (const float*)d_in[0];   // (B, 4)
    const float* W  = (const float*)d_in[1];   // (NL, 6)
    const float* ab = (const float*)d_in[2];   // (2,)
    float* out = (float*)d_out;                // (B, 4)
    const int B = in_sizes[0] / 4;
    const int nlayers = in_sizes[1] / 6;
    const int threads = 128;
    const int blocks = (B + threads - 1) / threads;
    qsim6_kernel<<<blocks, threads>>>(x, W, ab, out, nlayers, B);
}